// round 16
// baseline (speedup 1.0000x reference)
#include <cuda_runtime.h>
#include <cuda_fp16.h>
#include <cstdint>
#include <math.h>

#define Bb 2
#define Hh 16
#define Ss 2048
#define Dd 64
#define MT 256
#define KN 128
#define NTL (Ss/KN)
#define TPB 256
// q scale: log2(e) / TEMPERATURE  -> scores arrive in log2 domain
#define QSCALE 0.18033688011112042f

// scratch: K-hi [head][tile 16KB], then V-hi [head][tile 16KB]
#define SCR_TILE 16384
#define SCR_HEAD (NTL*SCR_TILE)            // 262144
#define SCR_TENSOR (32u*SCR_HEAD)          // 8388608
__device__ __align__(16) unsigned char g_scr[2u * SCR_TENSOR];
__device__ float g_rinv[32 * Ss];

// SMEM offsets (pass B): QH 32K | BUF0 32K (Khi|Vhi) | BUF1 32K | SENT 1K | STAGE 68K
#define SM_QH 0
#define SM_BUF0 32768
#define SM_BUF1 65536
#define SM_SENT 98304
#define SM_STAGE 99328                     // 256 rows x 68 words (fp16x2), stride-padded
#define STG_PITCH 68
#define SMEM_B_BYTES (99328 + 256*STG_PITCH*4)   // 168960
// SMEM offsets (pass A): QH 32K | BUF0 16K | BUF1 16K | SENT
#define SA_BUF0 32768
#define SA_BUF1 49152
#define SA_SENT 65536
#define SMEM_A_BYTES 66560

__device__ __forceinline__ uint32_t smem_u32(const void* p) {
    uint32_t a; asm("{ .reg .u64 t; cvta.to.shared.u64 t, %1; cvt.u32.u64 %0, t; }" : "=r"(a) : "l"(p));
    return a;
}
__device__ __forceinline__ uint32_t sw128(uint32_t off) { return off ^ ((off >> 3) & 0x70); }

__device__ __forceinline__ uint32_t cvt2h(float x0, float x1) {
    __half2 H = __floats2half2_rn(x0, x1);
    return *(uint32_t*)&H;
}
__device__ __forceinline__ float ex2(float x) {
    float r; asm("ex2.approx.f32 %0, %1;" : "=f"(r) : "f"(x)); return r;
}

__device__ __forceinline__ void ldsm4(uint32_t* r, uint32_t addr) {
    asm volatile("ldmatrix.sync.aligned.m8n8.x4.shared.b16 {%0,%1,%2,%3}, [%4];"
        : "=r"(r[0]), "=r"(r[1]), "=r"(r[2]), "=r"(r[3]) : "r"(addr));
}
__device__ __forceinline__ void ldsm4t(uint32_t* r, uint32_t addr) {
    asm volatile("ldmatrix.sync.aligned.m8n8.x4.trans.shared.b16 {%0,%1,%2,%3}, [%4];"
        : "=r"(r[0]), "=r"(r[1]), "=r"(r[2]), "=r"(r[3]) : "r"(addr));
}
__device__ __forceinline__ void mma16816(float* c, const uint32_t* a, uint32_t b0, uint32_t b1) {
    asm("mma.sync.aligned.m16n8k16.row.col.f32.f16.f16.f32 "
        "{%0,%1,%2,%3}, {%4,%5,%6,%7}, {%8,%9}, {%0,%1,%2,%3};"
        : "+f"(c[0]), "+f"(c[1]), "+f"(c[2]), "+f"(c[3])
        : "r"(a[0]), "r"(a[1]), "r"(a[2]), "r"(a[3]), "r"(b0), "r"(b1));
}
__device__ __forceinline__ void cp16(uint32_t saddr, const void* g) {
    asm volatile("cp.async.ca.shared.global [%0], [%1], 16;" :: "r"(saddr), "l"(g));
}
#define CP_COMMIT() asm volatile("cp.async.commit_group;" ::: "memory")
#define CP_WAIT0()  asm volatile("cp.async.wait_group 0;" ::: "memory")
#define CP_WAIT1()  asm volatile("cp.async.wait_group 1;" ::: "memory")

// ---------- conv: K,V -> fp16 hi, swizzled tile layout ----------
__global__ void __launch_bounds__(256, 4)
conv_kernel(const float* __restrict__ K, const float* __restrict__ V)
{
    const int idx = blockIdx.x * 256 + threadIdx.x;
    const int tensor = idx >> 19;
    const int c = idx & 524287;
    const int h = c >> 14;
    const int rem = c & 16383;
    const int j = rem >> 3, cc = rem & 7;
    const float* src = (tensor ? V : K) + (((size_t)h * Ss + j) * Dd) + cc * 8;
    float4 a = *(const float4*)src;
    float4 b2 = *(const float4*)(src + 4);
    uint4 H;
    H.x = cvt2h(a.x, a.y);   H.y = cvt2h(a.z, a.w);
    H.z = cvt2h(b2.x, b2.y); H.w = cvt2h(b2.z, b2.w);
    size_t base = (size_t)tensor * SCR_TENSOR + (size_t)h * SCR_HEAD + (size_t)(j >> 7) * SCR_TILE;
    uint32_t off = sw128((uint32_t)((j & 127) * 128 + cc * 16));
    *(uint4*)(g_scr + base + off) = H;
}

// ---------- pass A: rowsum inverses (qh·kh, log2 domain), 2 CTAs/SM ----------
__global__ void __launch_bounds__(256, 2)
passA_kernel(const float* __restrict__ Q, const float* __restrict__ SENT,
             const int* __restrict__ MASK)
{
    extern __shared__ char sm[];
    const uint32_t sb = smem_u32(sm);
    const int tid = threadIdx.x, lane = tid & 31, wid = tid >> 5;
    const int q0 = blockIdx.x * MT;
    const int head = blockIdx.y;
    const int b = head >> 4;
    const size_t head_off = (size_t)head * Ss;

    const unsigned char* scrK = g_scr + (size_t)head * SCR_HEAD;
    float* sentm = (float*)(sm + SA_SENT);
    const uint32_t bufb[2] = {sb + SA_BUF0, sb + SA_BUF1};

    {
        const float4* qg = (const float4*)(Q + (head_off + q0) * Dd);
        #pragma unroll
        for (int u = 0; u < 8; u++) {
            int idx = u * TPB + tid;
            int r = idx >> 3, c = idx & 7;
            float4 a = qg[r * 16 + c * 2], bq = qg[r * 16 + c * 2 + 1];
            uint4 H;
            H.x = cvt2h(a.x * QSCALE, a.y * QSCALE);
            H.y = cvt2h(a.z * QSCALE, a.w * QSCALE);
            H.z = cvt2h(bq.x * QSCALE, bq.y * QSCALE);
            H.w = cvt2h(bq.z * QSCALE, bq.w * QSCALE);
            *(uint4*)(sm + SM_QH + sw128((uint32_t)(r * 128 + c * 16))) = H;
        }
    }
    {
        #pragma unroll
        for (int u = 0; u < 4; u++) {
            int i = (u * TPB + tid) * 16;
            cp16(bufb[0] + i, scrK + i);
        }
        CP_COMMIT();
    }
    __syncthreads();

    uint32_t qh[2][4][4];
    #pragma unroll
    for (int rs = 0; rs < 2; rs++) {
        uint32_t rowq = (uint32_t)(wid * 32 + rs * 16 + (lane & 15));
        #pragma unroll
        for (int kb = 0; kb < 4; kb++)
            ldsm4(qh[rs][kb], sb + SM_QH + sw128(rowq * 128 + ((uint32_t)(lane >> 4) + 2 * kb) * 16));
    }

    const int cb = 2 * (lane & 3);
    float rsum[2][2] = {{0.f, 0.f}, {0.f, 0.f}};

    for (int t = 0; t < NTL; t++) {
        if (t + 1 < NTL) {
            const unsigned char* s = scrK + (size_t)(t + 1) * SCR_TILE;
            #pragma unroll
            for (int u = 0; u < 4; u++) {
                int i = (u * TPB + tid) * 16;
                cp16(bufb[(t + 1) & 1] + i, s + i);
            }
            CP_COMMIT();
        }
        if (tid < KN) {
            int j = t * KN + tid;
            sentm[(t & 1) * 128 + tid] = MASK[b * Ss + j] ? SENT[b * Ss + j] : 0.0f;
        }
        if (t + 1 < NTL) CP_WAIT1(); else CP_WAIT0();
        __syncthreads();

        const uint32_t kh_b = bufb[t & 1];
        const float* sm_s = sentm + (t & 1) * 128;
        #pragma unroll
        for (int nb = 0; nb < 16; nb++) {
            uint32_t bh[8];
            uint32_t rB = (uint32_t)(nb * 8 + (lane & 7)) * 128;
            uint32_t ch = (uint32_t)(lane >> 3) * 16;
            ldsm4(bh,     kh_b + sw128(rB + ch));
            ldsm4(bh + 4, kh_b + sw128(rB + ch + 64));
            float2 s2 = *(float2*)&sm_s[nb * 8 + cb];
            #pragma unroll
            for (int rs = 0; rs < 2; rs++) {
                float s0[4] = {0.f, 0.f, 0.f, 0.f};
                float s1[4] = {0.f, 0.f, 0.f, 0.f};
                mma16816(s0, qh[rs][0], bh[0], bh[1]);
                mma16816(s0, qh[rs][1], bh[2], bh[3]);
                mma16816(s1, qh[rs][2], bh[4], bh[5]);
                mma16816(s1, qh[rs][3], bh[6], bh[7]);
                rsum[rs][0] += ex2(s0[0] + s1[0]) * s2.x + ex2(s0[1] + s1[1]) * s2.y;
                rsum[rs][1] += ex2(s0[2] + s1[2]) * s2.x + ex2(s0[3] + s1[3]) * s2.y;
            }
        }
        __syncthreads();
    }

    #pragma unroll
    for (int rs = 0; rs < 2; rs++)
        #pragma unroll
        for (int hrow = 0; hrow < 2; hrow++) {
            float r = rsum[rs][hrow];
            r += __shfl_xor_sync(0xFFFFFFFFu, r, 1);
            r += __shfl_xor_sync(0xFFFFFFFFu, r, 2);
            if ((lane & 3) == 0)
                g_rinv[head * Ss + q0 + wid * 32 + rs * 16 + (lane >> 2) + hrow * 8] = 1.0f / r;
        }
}

// ---------- pass B: normalized attn (fp16-staged coalesced store) + PV ----------
__global__ void __launch_bounds__(TPB, 1)
attn_kernel(const float* __restrict__ Q, const float* __restrict__ SENT,
            const int* __restrict__ MASK,
            float* __restrict__ OUT, float* __restrict__ ATTN)
{
    extern __shared__ char sm[];
    const uint32_t sb = smem_u32(sm);
    const int tid = threadIdx.x, lane = tid & 31, wid = tid >> 5;
    const int q0 = blockIdx.x * MT;
    const int head = blockIdx.y;
    const int b = head >> 4;
    const size_t head_off = (size_t)head * Ss;

    const unsigned char* scrK = g_scr + (size_t)head * SCR_HEAD;
    const unsigned char* scrV = g_scr + SCR_TENSOR + (size_t)head * SCR_HEAD;
    float* sentm = (float*)(sm + SM_SENT);
    uint32_t* stg = (uint32_t*)(sm + SM_STAGE);
    const uint32_t bufb[2] = {sb + SM_BUF0, sb + SM_BUF1};

    {
        const float4* qg = (const float4*)(Q + (head_off + q0) * Dd);
        #pragma unroll
        for (int u = 0; u < 8; u++) {
            int idx = u * TPB + tid;
            int r = idx >> 3, c = idx & 7;
            float4 a = qg[r * 16 + c * 2], bq = qg[r * 16 + c * 2 + 1];
            uint4 H;
            H.x = cvt2h(a.x * QSCALE, a.y * QSCALE);
            H.y = cvt2h(a.z * QSCALE, a.w * QSCALE);
            H.z = cvt2h(bq.x * QSCALE, bq.y * QSCALE);
            H.w = cvt2h(bq.z * QSCALE, bq.w * QSCALE);
            *(uint4*)(sm + SM_QH + sw128((uint32_t)(r * 128 + c * 16))) = H;
        }
    }
    // tile 0: Khi|Vhi = 32KB
    {
        #pragma unroll
        for (int u = 0; u < 4; u++) {
            int i = (u * TPB + tid) * 16;
            cp16(bufb[0] + i, scrK + i);
            cp16(bufb[0] + 16384 + i, scrV + i);
        }
        CP_COMMIT();
    }
    __syncthreads();

    uint32_t qh[2][4][4];
    #pragma unroll
    for (int rs = 0; rs < 2; rs++) {
        uint32_t rowq = (uint32_t)(wid * 32 + rs * 16 + (lane & 15));
        #pragma unroll
        for (int kb = 0; kb < 4; kb++)
            ldsm4(qh[rs][kb], sb + SM_QH + sw128(rowq * 128 + ((uint32_t)(lane >> 4) + 2 * kb) * 16));
    }

    const int cb = 2 * (lane & 3);
    const int r0l[2] = {wid * 32 + (lane >> 2), wid * 32 + 16 + (lane >> 2)};

    float inv[2][2];
    #pragma unroll
    for (int rs = 0; rs < 2; rs++) {
        inv[rs][0] = g_rinv[head * Ss + q0 + r0l[rs]];
        inv[rs][1] = g_rinv[head * Ss + q0 + r0l[rs] + 8];
    }

    float oacc[2][8][4];
    #pragma unroll
    for (int rs = 0; rs < 2; rs++)
        #pragma unroll
        for (int nb = 0; nb < 8; nb++)
            #pragma unroll
            for (int i = 0; i < 4; i++) oacc[rs][nb][i] = 0.f;

    float* abase0 = ATTN + (head_off + q0) * (size_t)Ss;

    for (int t = 0; t < NTL; t++) {
        const int j0 = t * KN;
        if (t + 1 < NTL) {
            const unsigned char* ks = scrK + (size_t)(t + 1) * SCR_TILE;
            const unsigned char* vs = scrV + (size_t)(t + 1) * SCR_TILE;
            #pragma unroll
            for (int u = 0; u < 4; u++) {
                int i = (u * TPB + tid) * 16;
                cp16(bufb[(t + 1) & 1] + i, ks + i);
                cp16(bufb[(t + 1) & 1] + 16384 + i, vs + i);
            }
            CP_COMMIT();
        }
        if (tid < KN) {
            int j = j0 + tid;
            sentm[(t & 1) * 128 + tid] = MASK[b * Ss + j] ? SENT[b * Ss + j] : 0.0f;
        }
        if (t + 1 < NTL) CP_WAIT1(); else CP_WAIT0();
        __syncthreads();

        const uint32_t kh_b = bufb[t & 1];
        const uint32_t vh_b = kh_b + 16384;
        const float* sm_s = sentm + (t & 1) * 128;

        #pragma unroll
        for (int kb = 0; kb < 8; kb++) {
            uint32_t pa[2][4];
            #pragma unroll
            for (int nbi = 0; nbi < 2; nbi++) {
                const int nb = 2 * kb + nbi;
                uint32_t bh[8];
                uint32_t rB = (uint32_t)(nb * 8 + (lane & 7)) * 128;
                uint32_t ch = (uint32_t)(lane >> 3) * 16;
                ldsm4(bh,     kh_b + sw128(rB + ch));
                ldsm4(bh + 4, kh_b + sw128(rB + ch + 64));
                float2 s2 = *(float2*)&sm_s[nb * 8 + cb];
                const int cp = nb * 4 + (lane & 3);
                #pragma unroll
                for (int rs = 0; rs < 2; rs++) {
                    float s0[4] = {0.f, 0.f, 0.f, 0.f};
                    float s1[4] = {0.f, 0.f, 0.f, 0.f};
                    mma16816(s0, qh[rs][0], bh[0], bh[1]);
                    mma16816(s0, qh[rs][1], bh[2], bh[3]);
                    mma16816(s1, qh[rs][2], bh[4], bh[5]);
                    mma16816(s1, qh[rs][3], bh[6], bh[7]);
                    float p0 = ex2(s0[0] + s1[0]) * s2.x * inv[rs][0];
                    float p1 = ex2(s0[1] + s1[1]) * s2.y * inv[rs][0];
                    float p2 = ex2(s0[2] + s1[2]) * s2.x * inv[rs][1];
                    float p3 = ex2(s0[3] + s1[3]) * s2.y * inv[rs][1];
                    uint32_t w0 = cvt2h(p0, p1);
                    uint32_t w1 = cvt2h(p2, p3);
                    pa[rs][nbi * 2]     = w0;
                    pa[rs][nbi * 2 + 1] = w1;
                    stg[r0l[rs] * STG_PITCH + cp]       = w0;
                    stg[(r0l[rs] + 8) * STG_PITCH + cp] = w1;
                }
            }
            // PV (V-hi)
            uint32_t vh[16];
            uint32_t rV = (uint32_t)(kb * 16 + (lane & 15)) * 128;
            uint32_t chv = (uint32_t)(lane >> 4) * 16;
            #pragma unroll
            for (int qd = 0; qd < 4; qd++)
                ldsm4t(vh + 4 * qd, vh_b + sw128(rV + chv + qd * 32));
            #pragma unroll
            for (int rs = 0; rs < 2; rs++)
                #pragma unroll
                for (int nbd = 0; nbd < 8; nbd++)
                    mma16816(oacc[rs][nbd], pa[rs], vh[2 * nbd], vh[2 * nbd + 1]);
        }

        // ---- coalesced attn store: SMEM fp16 stage -> f32 gmem ----
        __syncthreads();
        {
            float* ab = abase0 + j0;
            #pragma unroll 4
            for (int it = 0; it < 32; it++) {
                int idx = it * TPB + tid;
                int row = idx >> 5, wq = idx & 31;
                uint2 two = *(const uint2*)(stg + row * STG_PITCH + wq * 2);
                __half2 h0 = *(__half2*)&two.x, h1 = *(__half2*)&two.y;
                float2 f0 = __half22float2(h0), f1 = __half22float2(h1);
                *(float4*)(ab + (size_t)row * Ss + wq * 4) =
                    make_float4(f0.x, f0.y, f1.x, f1.y);
            }
        }
        __syncthreads();
    }

    #pragma unroll
    for (int rs = 0; rs < 2; rs++) {
        float2* o0 = (float2*)(OUT + (head_off + q0 + r0l[rs]) * (size_t)Dd);
        float2* o1 = (float2*)(OUT + (head_off + q0 + r0l[rs] + 8) * (size_t)Dd);
        #pragma unroll
        for (int nbd = 0; nbd < 8; nbd++) {
            o0[nbd * 4 + (lane & 3)] = make_float2(oacc[rs][nbd][0], oacc[rs][nbd][1]);
            o1[nbd * 4 + (lane & 3)] = make_float2(oacc[rs][nbd][2], oacc[rs][nbd][3]);
        }
    }
}

extern "C" void kernel_launch(void* const* d_in, const int* in_sizes, int n_in,
                              void* d_out, int out_size)
{
    const float* q    = (const float*)d_in[0];
    const float* k    = (const float*)d_in[1];
    const float* v    = (const float*)d_in[2];
    const float* sent = (const float*)d_in[3];
    const int*   mask = (const int*)d_in[4];

    float* out  = (float*)d_out;                    // [B,H,S,D]
    float* attn = out + (size_t)Bb * Hh * Ss * Dd;  // [B,H,S,S]

    conv_kernel<<<4096, 256>>>(k, v);

    cudaFuncSetAttribute(passA_kernel, cudaFuncAttributeMaxDynamicSharedMemorySize, SMEM_A_BYTES);
    dim3 gridA(Ss / MT, Bb * Hh);
    passA_kernel<<<gridA, TPB, SMEM_A_BYTES>>>(q, sent, mask);

    cudaFuncSetAttribute(attn_kernel, cudaFuncAttributeMaxDynamicSharedMemorySize, SMEM_B_BYTES);
    dim3 gridB(Ss / MT, Bb * Hh);
    attn_kernel<<<gridB, TPB, SMEM_B_BYTES>>>(q, sent, mask, out, attn);
}

// round 17
// speedup vs baseline: 1.2524x; 1.2524x over previous
#include <cuda_runtime.h>
#include <cuda_fp16.h>
#include <cstdint>
#include <math.h>

#define Bb 2
#define Hh 16
#define Ss 2048
#define Dd 64
#define MT 256
#define KN 128
#define NTL (Ss/KN)
#define TPB 256
#define INV_TEMP 0.125f

// scratch: K-hi [head][tile 16KB], then V-hi [head][tile 16KB]
#define SCR_TILE 16384
#define SCR_HEAD (NTL*SCR_TILE)            // 262144
#define SCR_TENSOR (32u*SCR_HEAD)          // 8388608
__device__ __align__(16) unsigned char g_scr[2u * SCR_TENSOR];
__device__ float g_rinv[32 * Ss];

// SMEM offsets (pass B): QH 32K | BUF0 32K (Khi|Vhi) | BUF1 32K | SENT
#define SM_QH 0
#define SM_BUF0 32768
#define SM_BUF1 65536
#define SM_SENT 98304
#define SMEM_B_BYTES 99328
// SMEM offsets (pass A): QH 32K | BUF0 16K | BUF1 16K | SENT
#define SA_BUF0 32768
#define SA_BUF1 49152
#define SA_SENT 65536
#define SMEM_A_BYTES 66560

__device__ __forceinline__ uint32_t smem_u32(const void* p) {
    uint32_t a; asm("{ .reg .u64 t; cvta.to.shared.u64 t, %1; cvt.u32.u64 %0, t; }" : "=r"(a) : "l"(p));
    return a;
}
__device__ __forceinline__ uint32_t sw128(uint32_t off) { return off ^ ((off >> 3) & 0x70); }

__device__ __forceinline__ uint32_t cvt2h(float x0, float x1) {
    __half2 H = __floats2half2_rn(x0, x1);
    return *(uint32_t*)&H;
}

// streaming (evict-first) global stores: keep K/V scratch resident in L2
__device__ __forceinline__ void stg_cs_v2(float* p, float a, float b) {
    asm volatile("st.global.cs.v2.f32 [%0], {%1, %2};" :: "l"(p), "f"(a), "f"(b) : "memory");
}

__device__ __forceinline__ void ldsm4(uint32_t* r, uint32_t addr) {
    asm volatile("ldmatrix.sync.aligned.m8n8.x4.shared.b16 {%0,%1,%2,%3}, [%4];"
        : "=r"(r[0]), "=r"(r[1]), "=r"(r[2]), "=r"(r[3]) : "r"(addr));
}
__device__ __forceinline__ void ldsm4t(uint32_t* r, uint32_t addr) {
    asm volatile("ldmatrix.sync.aligned.m8n8.x4.trans.shared.b16 {%0,%1,%2,%3}, [%4];"
        : "=r"(r[0]), "=r"(r[1]), "=r"(r[2]), "=r"(r[3]) : "r"(addr));
}
__device__ __forceinline__ void mma16816(float* c, const uint32_t* a, uint32_t b0, uint32_t b1) {
    asm("mma.sync.aligned.m16n8k16.row.col.f32.f16.f16.f32 "
        "{%0,%1,%2,%3}, {%4,%5,%6,%7}, {%8,%9}, {%0,%1,%2,%3};"
        : "+f"(c[0]), "+f"(c[1]), "+f"(c[2]), "+f"(c[3])
        : "r"(a[0]), "r"(a[1]), "r"(a[2]), "r"(a[3]), "r"(b0), "r"(b1));
}
__device__ __forceinline__ void cp16(uint32_t saddr, const void* g) {
    asm volatile("cp.async.ca.shared.global [%0], [%1], 16;" :: "r"(saddr), "l"(g));
}
#define CP_COMMIT() asm volatile("cp.async.commit_group;" ::: "memory")
#define CP_WAIT0()  asm volatile("cp.async.wait_group 0;" ::: "memory")
#define CP_WAIT1()  asm volatile("cp.async.wait_group 1;" ::: "memory")

// ---------- conv: K,V -> fp16 hi, swizzled tile layout ----------
__global__ void __launch_bounds__(256, 4)
conv_kernel(const float* __restrict__ K, const float* __restrict__ V)
{
    const int idx = blockIdx.x * 256 + threadIdx.x;
    const int tensor = idx >> 19;
    const int c = idx & 524287;
    const int h = c >> 14;
    const int rem = c & 16383;
    const int j = rem >> 3, cc = rem & 7;
    const float* src = (tensor ? V : K) + (((size_t)h * Ss + j) * Dd) + cc * 8;
    float4 a = *(const float4*)src;
    float4 b2 = *(const float4*)(src + 4);
    uint4 H;
    H.x = cvt2h(a.x, a.y);   H.y = cvt2h(a.z, a.w);
    H.z = cvt2h(b2.x, b2.y); H.w = cvt2h(b2.z, b2.w);
    size_t base = (size_t)tensor * SCR_TENSOR + (size_t)h * SCR_HEAD + (size_t)(j >> 7) * SCR_TILE;
    uint32_t off = sw128((uint32_t)((j & 127) * 128 + cc * 16));
    *(uint4*)(g_scr + base + off) = H;
}

// ---------- pass A: rowsum inverses (qh·kh), 2 CTAs/SM, single wave ----------
__global__ void __launch_bounds__(256, 2)
passA_kernel(const float* __restrict__ Q, const float* __restrict__ SENT,
             const int* __restrict__ MASK)
{
    extern __shared__ char sm[];
    const uint32_t sb = smem_u32(sm);
    const int tid = threadIdx.x, lane = tid & 31, wid = tid >> 5;
    const int q0 = blockIdx.x * MT;
    const int head = blockIdx.y;
    const int b = head >> 4;
    const size_t head_off = (size_t)head * Ss;

    const unsigned char* scrK = g_scr + (size_t)head * SCR_HEAD;
    float* sentm = (float*)(sm + SA_SENT);
    const uint32_t bufb[2] = {sb + SA_BUF0, sb + SA_BUF1};

    {
        const float4* qg = (const float4*)(Q + (head_off + q0) * Dd);
        #pragma unroll
        for (int u = 0; u < 8; u++) {
            int idx = u * TPB + tid;
            int r = idx >> 3, c = idx & 7;
            float4 a = qg[r * 16 + c * 2], bq = qg[r * 16 + c * 2 + 1];
            uint4 H;
            H.x = cvt2h(a.x * INV_TEMP, a.y * INV_TEMP);
            H.y = cvt2h(a.z * INV_TEMP, a.w * INV_TEMP);
            H.z = cvt2h(bq.x * INV_TEMP, bq.y * INV_TEMP);
            H.w = cvt2h(bq.z * INV_TEMP, bq.w * INV_TEMP);
            *(uint4*)(sm + SM_QH + sw128((uint32_t)(r * 128 + c * 16))) = H;
        }
    }
    {
        #pragma unroll
        for (int u = 0; u < 4; u++) {
            int i = (u * TPB + tid) * 16;
            cp16(bufb[0] + i, scrK + i);
        }
        CP_COMMIT();
    }
    __syncthreads();

    uint32_t qh[2][4][4];
    #pragma unroll
    for (int rs = 0; rs < 2; rs++) {
        uint32_t rowq = (uint32_t)(wid * 32 + rs * 16 + (lane & 15));
        #pragma unroll
        for (int kb = 0; kb < 4; kb++)
            ldsm4(qh[rs][kb], sb + SM_QH + sw128(rowq * 128 + ((uint32_t)(lane >> 4) + 2 * kb) * 16));
    }

    const int cb = 2 * (lane & 3);
    float rsum[2][2] = {{0.f, 0.f}, {0.f, 0.f}};

    for (int t = 0; t < NTL; t++) {
        if (t + 1 < NTL) {
            const unsigned char* s = scrK + (size_t)(t + 1) * SCR_TILE;
            #pragma unroll
            for (int u = 0; u < 4; u++) {
                int i = (u * TPB + tid) * 16;
                cp16(bufb[(t + 1) & 1] + i, s + i);
            }
            CP_COMMIT();
        }
        if (tid < KN) {
            int j = t * KN + tid;
            sentm[(t & 1) * 128 + tid] = MASK[b * Ss + j] ? SENT[b * Ss + j] : 0.0f;
        }
        if (t + 1 < NTL) CP_WAIT1(); else CP_WAIT0();
        __syncthreads();

        const uint32_t kh_b = bufb[t & 1];
        const float* sm_s = sentm + (t & 1) * 128;
        #pragma unroll
        for (int nb = 0; nb < 16; nb++) {
            uint32_t bh[8];
            uint32_t rB = (uint32_t)(nb * 8 + (lane & 7)) * 128;
            uint32_t ch = (uint32_t)(lane >> 3) * 16;
            ldsm4(bh,     kh_b + sw128(rB + ch));
            ldsm4(bh + 4, kh_b + sw128(rB + ch + 64));
            float2 s2 = *(float2*)&sm_s[nb * 8 + cb];
            #pragma unroll
            for (int rs = 0; rs < 2; rs++) {
                float sacc[4] = {0.f, 0.f, 0.f, 0.f};
                #pragma unroll
                for (int kb = 0; kb < 4; kb++)
                    mma16816(sacc, qh[rs][kb], bh[2 * kb], bh[2 * kb + 1]);
                rsum[rs][0] += __expf(sacc[0]) * s2.x + __expf(sacc[1]) * s2.y;
                rsum[rs][1] += __expf(sacc[2]) * s2.x + __expf(sacc[3]) * s2.y;
            }
        }
        __syncthreads();
    }

    #pragma unroll
    for (int rs = 0; rs < 2; rs++)
        #pragma unroll
        for (int hrow = 0; hrow < 2; hrow++) {
            float r = rsum[rs][hrow];
            r += __shfl_xor_sync(0xFFFFFFFFu, r, 1);
            r += __shfl_xor_sync(0xFFFFFFFFu, r, 2);
            if ((lane & 3) == 0)
                g_rinv[head * Ss + q0 + wid * 32 + rs * 16 + (lane >> 2) + hrow * 8] = 1.0f / r;
        }
}

// ---------- pass B: normalized attn + PV (hi-only, bit-identical QK to pass A) ----------
__global__ void __launch_bounds__(TPB, 1)
attn_kernel(const float* __restrict__ Q, const float* __restrict__ SENT,
            const int* __restrict__ MASK,
            float* __restrict__ OUT, float* __restrict__ ATTN)
{
    extern __shared__ char sm[];
    const uint32_t sb = smem_u32(sm);
    const int tid = threadIdx.x, lane = tid & 31, wid = tid >> 5;
    const int q0 = blockIdx.x * MT;
    const int head = blockIdx.y;
    const int b = head >> 4;
    const size_t head_off = (size_t)head * Ss;

    const unsigned char* scrK = g_scr + (size_t)head * SCR_HEAD;
    const unsigned char* scrV = g_scr + SCR_TENSOR + (size_t)head * SCR_HEAD;
    float* sentm = (float*)(sm + SM_SENT);
    const uint32_t bufb[2] = {sb + SM_BUF0, sb + SM_BUF1};

    {
        const float4* qg = (const float4*)(Q + (head_off + q0) * Dd);
        #pragma unroll
        for (int u = 0; u < 8; u++) {
            int idx = u * TPB + tid;
            int r = idx >> 3, c = idx & 7;
            float4 a = qg[r * 16 + c * 2], bq = qg[r * 16 + c * 2 + 1];
            uint4 H;
            H.x = cvt2h(a.x * INV_TEMP, a.y * INV_TEMP);
            H.y = cvt2h(a.z * INV_TEMP, a.w * INV_TEMP);
            H.z = cvt2h(bq.x * INV_TEMP, bq.y * INV_TEMP);
            H.w = cvt2h(bq.z * INV_TEMP, bq.w * INV_TEMP);
            *(uint4*)(sm + SM_QH + sw128((uint32_t)(r * 128 + c * 16))) = H;
        }
    }
    // tile 0: Khi|Vhi = 32KB
    {
        #pragma unroll
        for (int u = 0; u < 4; u++) {
            int i = (u * TPB + tid) * 16;
            cp16(bufb[0] + i, scrK + i);
            cp16(bufb[0] + 16384 + i, scrV + i);
        }
        CP_COMMIT();
    }
    __syncthreads();

    uint32_t qh[2][4][4];
    #pragma unroll
    for (int rs = 0; rs < 2; rs++) {
        uint32_t rowq = (uint32_t)(wid * 32 + rs * 16 + (lane & 15));
        #pragma unroll
        for (int kb = 0; kb < 4; kb++)
            ldsm4(qh[rs][kb], sb + SM_QH + sw128(rowq * 128 + ((uint32_t)(lane >> 4) + 2 * kb) * 16));
    }

    const int cb = 2 * (lane & 3);

    float inv[2][2];
    float* arow[2][2];
    #pragma unroll
    for (int rs = 0; rs < 2; rs++) {
        int row0 = wid * 32 + rs * 16 + (lane >> 2);
        inv[rs][0] = g_rinv[head * Ss + q0 + row0];
        inv[rs][1] = g_rinv[head * Ss + q0 + row0 + 8];
        arow[rs][0] = ATTN + (head_off + q0 + row0) * (size_t)Ss;
        arow[rs][1] = arow[rs][0] + 8 * (size_t)Ss;
    }

    float oacc[2][8][4];
    #pragma unroll
    for (int rs = 0; rs < 2; rs++)
        #pragma unroll
        for (int nb = 0; nb < 8; nb++)
            #pragma unroll
            for (int i = 0; i < 4; i++) oacc[rs][nb][i] = 0.f;

    for (int t = 0; t < NTL; t++) {
        const int j0 = t * KN;
        if (t + 1 < NTL) {
            const unsigned char* ks = scrK + (size_t)(t + 1) * SCR_TILE;
            const unsigned char* vs = scrV + (size_t)(t + 1) * SCR_TILE;
            #pragma unroll
            for (int u = 0; u < 4; u++) {
                int i = (u * TPB + tid) * 16;
                cp16(bufb[(t + 1) & 1] + i, ks + i);
                cp16(bufb[(t + 1) & 1] + 16384 + i, vs + i);
            }
            CP_COMMIT();
        }
        if (tid < KN) {
            int j = j0 + tid;
            sentm[(t & 1) * 128 + tid] = MASK[b * Ss + j] ? SENT[b * Ss + j] : 0.0f;
        }
        if (t + 1 < NTL) CP_WAIT1(); else CP_WAIT0();
        __syncthreads();

        const uint32_t kh_b = bufb[t & 1];
        const uint32_t vh_b = kh_b + 16384;
        const float* sm_s = sentm + (t & 1) * 128;

        #pragma unroll
        for (int kb = 0; kb < 8; kb++) {
            uint32_t pa[2][4];
            #pragma unroll
            for (int nbi = 0; nbi < 2; nbi++) {
                const int nb = 2 * kb + nbi;
                uint32_t bh[8];
                uint32_t rB = (uint32_t)(nb * 8 + (lane & 7)) * 128;
                uint32_t ch = (uint32_t)(lane >> 3) * 16;
                ldsm4(bh,     kh_b + sw128(rB + ch));
                ldsm4(bh + 4, kh_b + sw128(rB + ch + 64));
                float2 s2 = *(float2*)&sm_s[nb * 8 + cb];
                #pragma unroll
                for (int rs = 0; rs < 2; rs++) {
                    float sa[4] = {0.f, 0.f, 0.f, 0.f};
                    #pragma unroll
                    for (int kd = 0; kd < 4; kd++)
                        mma16816(sa, qh[rs][kd], bh[2 * kd], bh[2 * kd + 1]);
                    float p0 = __expf(sa[0]) * s2.x * inv[rs][0];
                    float p1 = __expf(sa[1]) * s2.y * inv[rs][0];
                    float p2 = __expf(sa[2]) * s2.x * inv[rs][1];
                    float p3 = __expf(sa[3]) * s2.y * inv[rs][1];
                    stg_cs_v2(arow[rs][0] + j0 + nb * 8 + cb, p0, p1);
                    stg_cs_v2(arow[rs][1] + j0 + nb * 8 + cb, p2, p3);
                    pa[rs][nbi * 2]     = cvt2h(p0, p1);
                    pa[rs][nbi * 2 + 1] = cvt2h(p2, p3);
                }
            }
            // PV (V-hi)
            uint32_t vh[16];
            uint32_t rV = (uint32_t)(kb * 16 + (lane & 15)) * 128;
            uint32_t chv = (uint32_t)(lane >> 4) * 16;
            #pragma unroll
            for (int qd = 0; qd < 4; qd++)
                ldsm4t(vh + 4 * qd, vh_b + sw128(rV + chv + qd * 32));
            #pragma unroll
            for (int rs = 0; rs < 2; rs++)
                #pragma unroll
                for (int nbd = 0; nbd < 8; nbd++)
                    mma16816(oacc[rs][nbd], pa[rs], vh[2 * nbd], vh[2 * nbd + 1]);
        }
        __syncthreads();
    }

    #pragma unroll
    for (int rs = 0; rs < 2; rs++) {
        int row0 = wid * 32 + rs * 16 + (lane >> 2);
        float* o0 = OUT + (head_off + q0 + row0) * (size_t)Dd;
        float* o1 = OUT + (head_off + q0 + row0 + 8) * (size_t)Dd;
        #pragma unroll
        for (int nbd = 0; nbd < 8; nbd++) {
            stg_cs_v2(o0 + nbd * 8 + cb, oacc[rs][nbd][0], oacc[rs][nbd][1]);
            stg_cs_v2(o1 + nbd * 8 + cb, oacc[rs][nbd][2], oacc[rs][nbd][3]);
        }
    }
}

extern "C" void kernel_launch(void* const* d_in, const int* in_sizes, int n_in,
                              void* d_out, int out_size)
{
    const float* q    = (const float*)d_in[0];
    const float* k    = (const float*)d_in[1];
    const float* v    = (const float*)d_in[2];
    const float* sent = (const float*)d_in[3];
    const int*   mask = (const int*)d_in[4];

    float* out  = (float*)d_out;                    // [B,H,S,D]
    float* attn = out + (size_t)Bb * Hh * Ss * Dd;  // [B,H,S,S]

    conv_kernel<<<4096, 256>>>(k, v);

    cudaFuncSetAttribute(passA_kernel, cudaFuncAttributeMaxDynamicSharedMemorySize, SMEM_A_BYTES);
    dim3 gridA(Ss / MT, Bb * Hh);
    passA_kernel<<<gridA, TPB, SMEM_A_BYTES>>>(q, sent, mask);

    cudaFuncSetAttribute(attn_kernel, cudaFuncAttributeMaxDynamicSharedMemorySize, SMEM_B_BYTES);
    dim3 gridB(Ss / MT, Bb * Hh);
    attn_kernel<<<gridB, TPB, SMEM_B_BYTES>>>(q, sent, mask, out, attn);
}